// round 10
// baseline (speedup 1.0000x reference)
#include <cuda_runtime.h>
#include <cuda_fp16.h>
#include <cstdint>

typedef unsigned int u32;

#define NPG   64
#define IN_F  128
#define OUT_F 128

// smem layouts (u32 = half2 units), rows of 64 words (256B = 16 chunks of 16B),
// chunk-XOR swizzle: chunk' = chunk ^ (row & 7)
#define BT_WORDS (128 * 64)    // W^T as half2(k,k+1) pairs: row n, word kp
#define XT_WORDS (64 * 64)     // X as half2 pairs: row node, word kp
#define SMEM_BYTES ((BT_WORDS + XT_WORDS) * 4)   // 49152

__device__ __forceinline__ u32 pack_h2(float lo, float hi) {
    __half2 h = __floats2half2_rn(lo, hi);
    return *(u32*)&h;
}

__device__ __forceinline__ u32 smem_addr(const void* p) {
    return (u32)__cvta_generic_to_shared(p);
}

#define LDSM_X4(r0, r1, r2, r3, a) \
    asm volatile("ldmatrix.sync.aligned.m8n8.x4.shared.b16 {%0,%1,%2,%3}, [%4];" \
        : "=r"(r0), "=r"(r1), "=r"(r2), "=r"(r3) : "r"(a))

__device__ __forceinline__ void mma_f16(float* c, u32 a0, u32 a1, u32 a2, u32 a3,
                                        u32 b0, u32 b1)
{
    asm volatile(
        "mma.sync.aligned.m16n8k16.row.col.f32.f16.f16.f32 "
        "{%0,%1,%2,%3}, {%4,%5,%6,%7}, {%8,%9}, {%0,%1,%2,%3};"
        : "+f"(c[0]), "+f"(c[1]), "+f"(c[2]), "+f"(c[3])
        : "r"(a0), "r"(a1), "r"(a2), "r"(a3), "r"(b0), "r"(b1));
}

__global__ void __launch_bounds__(512, 2)
mhl_mma_kernel(const float* __restrict__ x,
               const int*   __restrict__ head,
               const float* __restrict__ kern,
               const float* __restrict__ bias,
               float*       __restrict__ out)
{
    extern __shared__ u32 smem[];
    u32* BT = smem;               // [128 n][64 kp] half2(W[2kp][n], W[2kp+1][n]), swizzled
    u32* XT = smem + BT_WORDS;    // [64 node][64 kp] half2(X[node][2kp], X[node][2kp+1]), swizzled

    const int tid  = threadIdx.x;
    const int wid  = tid >> 5;             // 16 warps: 4m x 4n
    const int lane = tid & 31;
    const int gid  = lane >> 2;
    const int tig  = lane & 3;
    const int g    = blockIdx.x;
    const int h    = __ldg(head + g);

    const int m0 = (wid >> 2) * 16;        // 0,16,32,48
    const int n0 = (wid & 3) * 32;         // 0,32,64,96

    // ---- stage W[h] -> BT (transposed, fp16 k-pairs, swizzled chunks) ----
    {
        const float* W = kern + (size_t)h * IN_F * OUT_F;
        #pragma unroll
        for (int it = 0; it < 4; it++) {
            const int idx = tid + it * 512;        // 2048 chunks: n x c16
            const int n   = idx & 127;
            const int c16 = idx >> 7;              // chunk = k 8c16..8c16+7
            const float* src = W + (size_t)(8 * c16) * OUT_F + n;   // coalesced per q
            uint4 o;
            o.x = pack_h2(src[0],          src[OUT_F]);
            o.y = pack_h2(src[2 * OUT_F],  src[3 * OUT_F]);
            o.z = pack_h2(src[4 * OUT_F],  src[5 * OUT_F]);
            o.w = pack_h2(src[6 * OUT_F],  src[7 * OUT_F]);
            *(uint4*)&BT[n * 64 + ((c16 ^ (n & 7)) << 2)] = o;
        }
    }
    // ---- stage X[g] -> XT (fp16 k-pairs, swizzled chunks) ----
    {
        const float4* X4 = (const float4*)(x + (size_t)g * NPG * IN_F);
        #pragma unroll
        for (int it = 0; it < 2; it++) {
            const int idx  = tid + it * 512;       // 1024 chunks: node x c16
            const int node = idx >> 4;
            const int c16  = idx & 15;
            float4 v0 = X4[node * 32 + c16 * 2];
            float4 v1 = X4[node * 32 + c16 * 2 + 1];
            uint4 o;
            o.x = pack_h2(v0.x, v0.y);
            o.y = pack_h2(v0.z, v0.w);
            o.z = pack_h2(v1.x, v1.y);
            o.w = pack_h2(v1.z, v1.w);
            *(uint4*)&XT[node * 64 + ((c16 ^ (node & 7)) << 2)] = o;
        }
    }
    __syncthreads();

    float acc[4][4];
    #pragma unroll
    for (int j = 0; j < 4; j++)
        #pragma unroll
        for (int r = 0; r < 4; r++)
            acc[j][r] = 0.0f;

    // ldmatrix per-lane address setup
    // A x4 groups: g0=(m0+0..7,k0) g1=(+8,k0) g2=(0..7,k0+8) g3=(+8,k0+8)
    const int arow = m0 + (lane & 7) + 8 * ((lane >> 3) & 1);
    const int akc  = (lane >> 4) & 1;              // chunk offset 0/1
    const u32 abase = smem_addr(&XT[arow * 64]);
    const int ae = arow & 7;
    // B x4 groups: g0=(n+0..7,k0) g1=(same,k0+8) g2=(n+8..15,k0) g3=(+8,k0+8)
    const int brow = (lane & 7) + 8 * ((lane >> 4) & 1);
    const int bkc  = (lane >> 3) & 1;
    const u32 bbase0 = smem_addr(&BT[(n0 + brow) * 64]);
    const u32 bbase1 = smem_addr(&BT[(n0 + 16 + brow) * 64]);
    const int be0 = (n0 + brow) & 7;
    const int be1 = (n0 + 16 + brow) & 7;

    #pragma unroll
    for (int s = 0; s < 8; s++) {
        u32 a0, a1, a2, a3;
        {
            const int c = (2 * s + akc) ^ ae;
            LDSM_X4(a0, a1, a2, a3, abase + (c << 4));
        }
        u32 b00, b10, b01, b11, b02, b12, b03, b13;
        {
            const int c0 = (2 * s + bkc) ^ be0;
            LDSM_X4(b00, b10, b01, b11, bbase0 + (c0 << 4));
            const int c1 = (2 * s + bkc) ^ be1;
            LDSM_X4(b02, b12, b03, b13, bbase1 + (c1 << 4));
        }
        mma_f16(acc[0], a0, a1, a2, a3, b00, b10);
        mma_f16(acc[1], a0, a1, a2, a3, b01, b11);
        mma_f16(acc[2], a0, a1, a2, a3, b02, b12);
        mma_f16(acc[3], a0, a1, a2, a3, b03, b13);
    }

    // ---- epilogue: bias + coalesced float2 stores ----
    float bb[4][2];
    #pragma unroll
    for (int j = 0; j < 4; j++) {
        const int col = n0 + 8 * j + 2 * tig;
        bb[j][0] = __ldg(bias + (size_t)h * OUT_F + col);
        bb[j][1] = __ldg(bias + (size_t)h * OUT_F + col + 1);
    }

    const int node0 = g * NPG + m0 + gid;
    #pragma unroll
    for (int j = 0; j < 4; j++) {
        const int col = n0 + 8 * j + 2 * tig;
        float2 v0 = make_float2(acc[j][0] + bb[j][0], acc[j][1] + bb[j][1]);
        float2 v1 = make_float2(acc[j][2] + bb[j][0], acc[j][3] + bb[j][1]);
        *(float2*)&out[(size_t)node0 * OUT_F + col]       = v0;
        *(float2*)&out[(size_t)(node0 + 8) * OUT_F + col] = v1;
    }
}

extern "C" void kernel_launch(void* const* d_in, const int* in_sizes, int n_in,
                              void* d_out, int out_size)
{
    const float* inputs = (const float*)d_in[0];
    const int*   head   = (const int*)d_in[2];
    const float* kern   = (const float*)d_in[3];
    const float* bias   = (const float*)d_in[4];
    float*       out    = (float*)d_out;
    const int n_graphs  = in_sizes[2];   // 256

    static bool attr_set = false;
    if (!attr_set) {
        cudaFuncSetAttribute(mhl_mma_kernel, cudaFuncAttributeMaxDynamicSharedMemorySize, SMEM_BYTES);
        attr_set = true;
    }
    mhl_mma_kernel<<<n_graphs, 512, SMEM_BYTES>>>(inputs, head, kern, bias, out);
}

// round 11
// speedup vs baseline: 1.0269x; 1.0269x over previous
#include <cuda_runtime.h>
#include <cuda_fp16.h>
#include <cstdint>

typedef unsigned int u32;

#define NPG   64
#define IN_F  128
#define OUT_F 128

// smem images (fp16), 256B rows = 16 chunks of 16B, swizzle chunk' = chunk ^ (row & 7)
#define WK_WORDS (128 * 64)   // W [k][n] halfs  (32 KB)
#define XT_WORDS (64 * 64)    // X [node][k] halfs (16 KB)
#define SMEM_BYTES ((WK_WORDS + XT_WORDS) * 4)   // 49152

__device__ __forceinline__ u32 pack_h2(float lo, float hi) {
    __half2 h = __floats2half2_rn(lo, hi);
    return *(u32*)&h;
}
__device__ __forceinline__ u32 smem_addr(const void* p) {
    return (u32)__cvta_generic_to_shared(p);
}

#define LDSM_X4(r0, r1, r2, r3, a) \
    asm volatile("ldmatrix.sync.aligned.m8n8.x4.shared.b16 {%0,%1,%2,%3}, [%4];" \
        : "=r"(r0), "=r"(r1), "=r"(r2), "=r"(r3) : "r"(a))
#define LDSM_X4_T(r0, r1, r2, r3, a) \
    asm volatile("ldmatrix.sync.aligned.m8n8.x4.trans.shared.b16 {%0,%1,%2,%3}, [%4];" \
        : "=r"(r0), "=r"(r1), "=r"(r2), "=r"(r3) : "r"(a))

__device__ __forceinline__ void mma_f16(float* c, u32 a0, u32 a1, u32 a2, u32 a3,
                                        u32 b0, u32 b1)
{
    asm volatile(
        "mma.sync.aligned.m16n8k16.row.col.f32.f16.f16.f32 "
        "{%0,%1,%2,%3}, {%4,%5,%6,%7}, {%8,%9}, {%0,%1,%2,%3};"
        : "+f"(c[0]), "+f"(c[1]), "+f"(c[2]), "+f"(c[3])
        : "r"(a0), "r"(a1), "r"(a2), "r"(a3), "r"(b0), "r"(b1));
}

__global__ void __launch_bounds__(256, 2)
mhl_mma_kernel(const float* __restrict__ x,
               const int*   __restrict__ head,
               const float* __restrict__ kern,
               const float* __restrict__ bias,
               float*       __restrict__ out)
{
    extern __shared__ u32 smem[];
    u32* Wk = smem;               // [128 k][64 words] halfs n0..n127, swizzled chunks
    u32* XT = smem + WK_WORDS;    // [64 node][64 words] halfs k0..k127, swizzled chunks

    const int tid  = threadIdx.x;
    const int wid  = tid >> 5;             // 8 warps: 2m x 4n
    const int lane = tid & 31;
    const int gid  = lane >> 2;
    const int tig  = lane & 3;
    const int g    = blockIdx.x;
    const int h    = __ldg(head + g);

    const int m0 = (wid >> 2) * 32;        // 0, 32
    const int n0 = (wid & 3) * 32;         // 0, 32, 64, 96

    // ---- stage W[h][k][n] -> Wk fp16 (2 LDG.128 + STS.128 per chunk) ----
    {
        const float* W = kern + (size_t)h * IN_F * OUT_F;
        #pragma unroll
        for (int it = 0; it < 8; it++) {
            const int idx = tid + it * 256;         // 2048 chunks
            const int k   = idx >> 4;
            const int nc  = idx & 15;               // n-chunk: halfs 8nc..8nc+7
            const float4* src = (const float4*)(W + k * OUT_F + nc * 8);
            float4 v0 = src[0], v1 = src[1];
            uint4 o;
            o.x = pack_h2(v0.x, v0.y);
            o.y = pack_h2(v0.z, v0.w);
            o.z = pack_h2(v1.x, v1.y);
            o.w = pack_h2(v1.z, v1.w);
            *(uint4*)&Wk[k * 64 + ((nc ^ (k & 7)) << 2)] = o;
        }
    }
    // ---- stage X[g][node][k] -> XT fp16 ----
    {
        const float4* X4 = (const float4*)(x + (size_t)g * NPG * IN_F);
        #pragma unroll
        for (int it = 0; it < 4; it++) {
            const int idx  = tid + it * 256;        // 1024 chunks
            const int node = idx >> 4;
            const int kc   = idx & 15;              // k-chunk: halfs 8kc..8kc+7
            float4 v0 = X4[node * 32 + kc * 2];
            float4 v1 = X4[node * 32 + kc * 2 + 1];
            uint4 o;
            o.x = pack_h2(v0.x, v0.y);
            o.y = pack_h2(v0.z, v0.w);
            o.z = pack_h2(v1.x, v1.y);
            o.w = pack_h2(v1.z, v1.w);
            *(uint4*)&XT[node * 64 + ((kc ^ (node & 7)) << 2)] = o;
        }
    }
    __syncthreads();

    float acc[2][4][4];
    #pragma unroll
    for (int i = 0; i < 2; i++)
        #pragma unroll
        for (int j = 0; j < 4; j++)
            #pragma unroll
            for (int r = 0; r < 4; r++)
                acc[i][j][r] = 0.0f;

    // A (non-trans LDSM, validated R10): rows = m, chunks along k
    const int arow0 = m0 + (lane & 7) + 8 * ((lane >> 3) & 1);
    const int akc   = (lane >> 4) & 1;
    const u32 abase0 = smem_addr(&XT[arow0 * 64]);
    const u32 abase1 = smem_addr(&XT[(arow0 + 16) * 64]);
    const int ae0 = arow0 & 7, ae1 = (arow0 + 16) & 7;

    // B (trans LDSM): rows = k, chunks along n
    const int brow_off = (lane & 7) + 8 * ((lane >> 3) & 1);    // within k16 block
    const int bnc_off  = (lane >> 4) & 1;                       // n-chunk 0/1 within pair

    #pragma unroll
    for (int s = 0; s < 8; s++) {
        // A fragments: 2 m-tiles
        u32 a0[4], a1[4];
        LDSM_X4(a0[0], a0[1], a0[2], a0[3], abase0 + ((((2 * s) + akc) ^ ae0) << 4));
        LDSM_X4(a1[0], a1[1], a1[2], a1[3], abase1 + ((((2 * s) + akc) ^ ae1) << 4));
        // B fragments: 2 trans-LDSM cover 4 n-tiles (k16 x n16 each)
        const int krow = 16 * s + brow_off;
        const u32 bstride = smem_addr(&Wk[krow * 64]);
        u32 b[2][4];
        #pragma unroll
        for (int p = 0; p < 2; p++) {
            const int nc = (n0 >> 3) + 2 * p + bnc_off;
            LDSM_X4_T(b[p][0], b[p][1], b[p][2], b[p][3],
                      bstride + ((nc ^ (krow & 7)) << 4));
        }
        // 16 MMAs, 8 independent chains
        #pragma unroll
        for (int j = 0; j < 4; j++) {
            const int p = j >> 1, q = j & 1;
            mma_f16(acc[0][j], a0[0], a0[1], a0[2], a0[3], b[p][2 * q], b[p][2 * q + 1]);
            mma_f16(acc[1][j], a1[0], a1[1], a1[2], a1[3], b[p][2 * q], b[p][2 * q + 1]);
        }
    }

    // ---- epilogue: bias + coalesced float2 stores ----
    float bb[4][2];
    #pragma unroll
    for (int j = 0; j < 4; j++) {
        const int col = n0 + 8 * j + 2 * tig;
        bb[j][0] = __ldg(bias + (size_t)h * OUT_F + col);
        bb[j][1] = __ldg(bias + (size_t)h * OUT_F + col + 1);
    }

    #pragma unroll
    for (int i = 0; i < 2; i++) {
        const int node0 = g * NPG + m0 + 16 * i + gid;
        #pragma unroll
        for (int j = 0; j < 4; j++) {
            const int col = n0 + 8 * j + 2 * tig;
            float2 v0 = make_float2(acc[i][j][0] + bb[j][0], acc[i][j][1] + bb[j][1]);
            float2 v1 = make_float2(acc[i][j][2] + bb[j][0], acc[i][j][3] + bb[j][1]);
            *(float2*)&out[(size_t)node0 * OUT_F + col]       = v0;
            *(float2*)&out[(size_t)(node0 + 8) * OUT_F + col] = v1;
        }
    }
}

extern "C" void kernel_launch(void* const* d_in, const int* in_sizes, int n_in,
                              void* d_out, int out_size)
{
    const float* inputs = (const float*)d_in[0];
    const int*   head   = (const int*)d_in[2];
    const float* kern   = (const float*)d_in[3];
    const float* bias   = (const float*)d_in[4];
    float*       out    = (float*)d_out;
    const int n_graphs  = in_sizes[2];   // 256

    static bool attr_set = false;
    if (!attr_set) {
        cudaFuncSetAttribute(mhl_mma_kernel, cudaFuncAttributeMaxDynamicSharedMemorySize, SMEM_BYTES);
        attr_set = true;
    }
    mhl_mma_kernel<<<n_graphs, 256, SMEM_BYTES>>>(inputs, head, kern, bias, out);
}